// round 8
// baseline (speedup 1.0000x reference)
#include <cuda_runtime.h>
#include <math.h>

#define Bb 32
#define Hh 32
#define Ll 32768
#define NTOT (Bb*Ll)

// ---------------- scratch ----------------
__device__ float2 g_phi[NTOT];        // 8 MB
__device__ float2 g_psi[NTOT];        // 8 MB
__device__ float4 g_beta[2*NTOT];     // 32 MB ; after k_stats3 holds wb (in-place)

__device__ double g_sum1[4], g_ssq1[4];
__device__ double g_sum2[4], g_ssq2[4];
__device__ double g_sum3[8], g_ssq3[8];
__device__ double g_sum4[32], g_ssq4[32];

__device__ unsigned g_cnt1, g_cnt2, g_cnt3, g_cnt4;   // zero-init; reset by finalizers

__device__ float g_a1[16], g_c1[16];
__device__ float g_a2[4],  g_c2[4];
__device__ float g_a3[8],  g_c3[8];
__device__ float g_a4[32], g_c4[32];

// ---------------- generic helpers ----------------
template<int NCH>
__device__ __forceinline__ void block_reduce_atomic(const float* acc, double* sums, double* ssqs) {
    __shared__ float red[8][2*NCH];
    int lane = threadIdx.x & 31, warp = threadIdx.x >> 5;
    #pragma unroll
    for (int j = 0; j < 2*NCH; j++) {
        float v = acc[j];
        #pragma unroll
        for (int o = 16; o; o >>= 1) v += __shfl_down_sync(0xffffffffu, v, o);
        if (lane == 0) red[warp][j] = v;
    }
    __syncthreads();
    for (int j = threadIdx.x; j < 2*NCH; j += blockDim.x) {
        float s = 0.f;
        #pragma unroll
        for (int w = 0; w < 8; w++) s += red[w][j];
        if (j < NCH) atomicAdd(&sums[j], (double)s);
        else         atomicAdd(&ssqs[j-NCH], (double)s);
    }
}

// last-block-done detector; returns true for every thread of the last block
__device__ __forceinline__ bool last_block(unsigned* cnt) {
    __shared__ int s_last;
    __threadfence();
    if (threadIdx.x == 0)
        s_last = (atomicAdd(cnt, 1u) == gridDim.x - 1);
    __syncthreads();
    return s_last != 0;
}

// generic finalize for NCH channels (run inside last block)
template<int NCH>
__device__ __forceinline__ void finalize_bn(const double* sums, const double* ssqs,
        const float* __restrict__ g, const float* __restrict__ be,
        float* a_out, float* c_out, double* sums_rst, double* ssqs_rst, unsigned* cnt) {
    int j = threadIdx.x;
    if (j < NCH) {
        double mean = __ldcg(&sums[j]) / (double)NTOT;
        double var  = __ldcg(&ssqs[j]) / (double)NTOT - mean * mean;
        float av = g[j] * (float)(1.0 / sqrt(var + 1e-5));
        a_out[j] = av;
        c_out[j] = be[j] - (float)mean * av;
        sums_rst[j] = 0.0; ssqs_rst[j] = 0.0;
    }
    if (j == 0) *cnt = 0;
}

// stage phi/psi tiles (halo +-3) into channel-split smem planes
template<int T>
__device__ __forceinline__ void stage_tiles(int b, int l0,
        float* s_ph0, float* s_ph1, float* s_ps0, float* s_ps1) {
    size_t base = (size_t)b * Ll;
    for (int i = threadIdx.x; i < T; i += 256) {
        float2 p = g_phi[base + l0 + i];
        s_ph0[i] = p.x; s_ph1[i] = p.y;
    }
    for (int i = threadIdx.x; i < T + 6; i += 256) {
        int l = l0 + i - 3;
        float2 p = (l >= 0 && l < Ll) ? g_psi[base + l] : make_float2(0.f, 0.f);
        s_ps0[i] = p.x; s_ps1[i] = p.y;
    }
}

// stage packed params for stage-1 (BN1 affine + conv_w1)
__device__ __forceinline__ void stage_params_t(float2* s_ac1, float4* s_w1t, float4* s_b1v,
        const float* __restrict__ w1, const float* __restrict__ b1) {
    int t = threadIdx.x;
    if (t < 16) {
        s_ac1[t] = make_float2(g_a1[t], g_c1[t]);
        s_w1t[t] = make_float4(w1[t], w1[16+t], w1[32+t], w1[48+t]);
    }
    if (t == 16) *s_b1v = make_float4(b1[0], b1[1], b1[2], b1[3]);
}

// stage packed params for stage-2 (BN2 affine + conv_w2)
__device__ __forceinline__ void stage_params_2(float4* s_w2v, float* s_b2,
        float4* s_a2v, float4* s_c2v,
        const float* __restrict__ w2, const float* __restrict__ b2) {
    int t = threadIdx.x;
    if (t >= 32 && t < 40) {
        int o = t - 32;
        s_w2v[o] = make_float4(w2[o*4], w2[o*4+1], w2[o*4+2], w2[o*4+3]);
        s_b2[o]  = b2[o];
    }
    if (t == 40) *s_a2v = make_float4(g_a2[0], g_a2[1], g_a2[2], g_a2[3]);
    if (t == 41) *s_c2v = make_float4(g_c2[0], g_c2[1], g_c2[2], g_c2[3]);
}

// load 4-element windows from smem planes into registers (LDS.128)
__device__ __forceinline__ void load_windows(
        const float* s_ph0, const float* s_ph1,
        const float* s_ps0, const float* s_ps1, int li0,
        float ph0[4], float ph1[4], float ps0[12], float ps1[12]) {
    *reinterpret_cast<float4*>(ph0) = *reinterpret_cast<const float4*>(s_ph0 + li0);
    *reinterpret_cast<float4*>(ph1) = *reinterpret_cast<const float4*>(s_ph1 + li0);
    #pragma unroll
    for (int k = 0; k < 3; k++) {
        *reinterpret_cast<float4*>(ps0 + 4*k) = *reinterpret_cast<const float4*>(s_ps0 + li0 + 4*k);
        *reinterpret_cast<float4*>(ps1 + 4*k) = *reinterpret_cast<const float4*>(s_ps1 + li0 + 4*k);
    }
}

// t for 4 consecutive elements from register windows
__device__ __forceinline__ void t4_compute(
        const float ph0[4], const float ph1[4],
        const float ps0[12], const float ps1[12],
        const float2* s_ac1, const float4* s_w1t, float4 b1v,
        float t[4][4]) {
    #pragma unroll
    for (int e = 0; e < 4; e++) {
        t[e][0] = b1v.x; t[e][1] = b1v.y; t[e][2] = b1v.z; t[e][3] = b1v.w;
    }
    {
        float2 ac = s_ac1[0]; float4 w = s_w1t[0];
        #pragma unroll
        for (int e = 0; e < 4; e++) {
            float v = fmaxf(fmaf(ac.x, ph0[e], ac.y), 0.f);
            t[e][0] = fmaf(w.x, v, t[e][0]); t[e][1] = fmaf(w.y, v, t[e][1]);
            t[e][2] = fmaf(w.z, v, t[e][2]); t[e][3] = fmaf(w.w, v, t[e][3]);
        }
    }
    {
        float2 ac = s_ac1[1]; float4 w = s_w1t[1];
        #pragma unroll
        for (int e = 0; e < 4; e++) {
            float v = fmaxf(fmaf(ac.x, ph1[e], ac.y), 0.f);
            t[e][0] = fmaf(w.x, v, t[e][0]); t[e][1] = fmaf(w.y, v, t[e][1]);
            t[e][2] = fmaf(w.z, v, t[e][2]); t[e][3] = fmaf(w.w, v, t[e][3]);
        }
    }
    #pragma unroll
    for (int j = 0; j < 7; j++) {
        float2 ac = s_ac1[2+j]; float4 w = s_w1t[2+j];
        #pragma unroll
        for (int e = 0; e < 4; e++) {
            float v = fmaxf(fmaf(ac.x, ps0[e+j], ac.y), 0.f);
            t[e][0] = fmaf(w.x, v, t[e][0]); t[e][1] = fmaf(w.y, v, t[e][1]);
            t[e][2] = fmaf(w.z, v, t[e][2]); t[e][3] = fmaf(w.w, v, t[e][3]);
        }
    }
    #pragma unroll
    for (int j = 0; j < 7; j++) {
        float2 ac = s_ac1[9+j]; float4 w = s_w1t[9+j];
        #pragma unroll
        for (int e = 0; e < 4; e++) {
            float v = fmaxf(fmaf(ac.x, ps1[e+j], ac.y), 0.f);
            t[e][0] = fmaf(w.x, v, t[e][0]); t[e][1] = fmaf(w.y, v, t[e][1]);
            t[e][2] = fmaf(w.z, v, t[e][2]); t[e][3] = fmaf(w.w, v, t[e][3]);
        }
    }
}

// stage-2: t -> w8 (pre-beta conv weight output), 4 elements
__device__ __forceinline__ void w8_compute(const float t[4][4],
        float4 a2v, float4 c2v, const float4* s_w2v, const float* s_b2,
        float w8[4][8]) {
    float u[4][4];
    #pragma unroll
    for (int e = 0; e < 4; e++) {
        u[e][0] = fmaxf(fmaf(a2v.x, t[e][0], c2v.x), 0.f);
        u[e][1] = fmaxf(fmaf(a2v.y, t[e][1], c2v.y), 0.f);
        u[e][2] = fmaxf(fmaf(a2v.z, t[e][2], c2v.z), 0.f);
        u[e][3] = fmaxf(fmaf(a2v.w, t[e][3], c2v.w), 0.f);
    }
    #pragma unroll
    for (int o = 0; o < 8; o++) {
        float4 w = s_w2v[o]; float bb = s_b2[o];
        #pragma unroll
        for (int e = 0; e < 4; e++) {
            float v = fmaf(w.x, u[e][0], bb);
            v = fmaf(w.y, u[e][1], v);
            v = fmaf(w.z, u[e][2], v);
            v = fmaf(w.w, u[e][3], v);
            w8[e][o] = v;
        }
    }
}

// ---------------- kernels ----------------

// P1: x -> phi, psi, beta ; raw moments of phi/psi ; last block finalizes BN1
__global__ void __launch_bounds__(256, 3) k_proj(
        const float* __restrict__ x,
        const float* __restrict__ w_phi, const float* __restrict__ b_phi,
        const float* __restrict__ w_psi, const float* __restrict__ b_psi,
        const float* __restrict__ w_beta, const float* __restrict__ b_beta,
        const float* __restrict__ gcat, const float* __restrict__ becat) {
    __shared__ float s_wphi[64], s_wpsi[64], s_wbeta[256], s_b[12];
    for (int i = threadIdx.x; i < 64; i += 256) { s_wphi[i] = w_phi[i]; s_wpsi[i] = w_psi[i]; }
    for (int i = threadIdx.x; i < 256; i += 256) s_wbeta[i] = w_beta[i];
    if (threadIdx.x < 2) { s_b[threadIdx.x] = b_phi[threadIdx.x]; s_b[2+threadIdx.x] = b_psi[threadIdx.x]; }
    if (threadIdx.x < 8) s_b[4+threadIdx.x] = b_beta[threadIdx.x];
    __syncthreads();

    int b  = blockIdx.x >> 5;
    int l0 = ((blockIdx.x & 31) << 10) + (threadIdx.x << 2);

    float ph0[4], ph1[4], ps0[4], ps1[4], bt[8][4];
    #pragma unroll
    for (int i = 0; i < 4; i++) {
        ph0[i]=s_b[0]; ph1[i]=s_b[1]; ps0[i]=s_b[2]; ps1[i]=s_b[3];
        #pragma unroll
        for (int o = 0; o < 8; o++) bt[o][i] = s_b[4+o];
    }
    const float* xb = x + (size_t)b * Hh * Ll + l0;
    #pragma unroll 8
    for (int c = 0; c < 32; c++) {
        float4 xv = __ldcs(reinterpret_cast<const float4*>(xb + (size_t)c * Ll));
        float xa[4] = {xv.x, xv.y, xv.z, xv.w};
        float wp0 = s_wphi[c], wp1 = s_wphi[32+c];
        float wq0 = s_wpsi[c], wq1 = s_wpsi[32+c];
        #pragma unroll
        for (int i = 0; i < 4; i++) {
            ph0[i] = fmaf(wp0, xa[i], ph0[i]); ph1[i] = fmaf(wp1, xa[i], ph1[i]);
            ps0[i] = fmaf(wq0, xa[i], ps0[i]); ps1[i] = fmaf(wq1, xa[i], ps1[i]);
        }
        #pragma unroll
        for (int o = 0; o < 8; o++) {
            float w = s_wbeta[o*32 + c];
            #pragma unroll
            for (int i = 0; i < 4; i++) bt[o][i] = fmaf(w, xa[i], bt[o][i]);
        }
    }
    size_t base = (size_t)b * Ll + l0;
    float acc[8] = {0,0,0,0,0,0,0,0};
    #pragma unroll
    for (int i = 0; i < 4; i++) {
        g_phi[base+i] = make_float2(ph0[i], ph1[i]);
        g_psi[base+i] = make_float2(ps0[i], ps1[i]);
        g_beta[2*(base+i)  ] = make_float4(bt[0][i], bt[1][i], bt[2][i], bt[3][i]);
        g_beta[2*(base+i)+1] = make_float4(bt[4][i], bt[5][i], bt[6][i], bt[7][i]);
        acc[0]+=ph0[i]; acc[4]+=ph0[i]*ph0[i];
        acc[1]+=ph1[i]; acc[5]+=ph1[i]*ph1[i];
        acc[2]+=ps0[i]; acc[6]+=ps0[i]*ps0[i];
        acc[3]+=ps1[i]; acc[7]+=ps1[i]*ps1[i];
    }
    block_reduce_atomic<4>(acc, g_sum1, g_ssq1);

    // ---- last block: finalize BN1 (16 cat channels with edge corrections) ----
    if (last_block(&g_cnt1)) {
        int ch = threadIdx.x;
        if (ch < 16) {
            double sum, ssq;
            if (ch < 2) { sum = __ldcg(&g_sum1[ch]); ssq = __ldcg(&g_ssq1[ch]); }
            else {
                int c = (ch - 2) / 7, j = (ch - 2) % 7, s = j - 3;
                sum = __ldcg(&g_sum1[2+c]); ssq = __ldcg(&g_ssq1[2+c]);
                if (s > 0) {
                    for (int bb2 = 0; bb2 < 32; bb2++)
                        for (int i = 0; i < s; i++) {
                            float2 p = __ldcg(&g_psi[(size_t)bb2 * Ll + i]);
                            double v = (c == 0) ? p.x : p.y;
                            sum -= v; ssq -= v*v;
                        }
                } else if (s < 0) {
                    for (int bb2 = 0; bb2 < 32; bb2++)
                        for (int i = 0; i < -s; i++) {
                            float2 p = __ldcg(&g_psi[(size_t)bb2 * Ll + Ll + s + i]);
                            double v = (c == 0) ? p.x : p.y;
                            sum -= v; ssq -= v*v;
                        }
                }
            }
            double mean = sum / (double)NTOT;
            double var  = ssq / (double)NTOT - mean * mean;
            float a = gcat[ch] * (float)(1.0 / sqrt(var + 1e-5));
            g_a1[ch] = a;
            g_c1[ch] = becat[ch] - (float)mean * a;
            if (ch < 4) { g_sum1[ch] = 0.0; g_ssq1[ch] = 0.0; }
        }
        if (threadIdx.x == 0) g_cnt1 = 0;
    }
}

// P2: moments of t ; last block finalizes BN2
__global__ void __launch_bounds__(256, 4) k_stats2(
        const float* __restrict__ w1, const float* __restrict__ b1,
        const float* __restrict__ gim, const float* __restrict__ beim) {
    __shared__ float2 s_ac1[16];
    __shared__ float4 s_w1t[16];
    __shared__ float4 s_b1v;
    __shared__ __align__(16) float s_ph0[1024], s_ph1[1024], s_ps0[1040], s_ps1[1040];
    stage_params_t(s_ac1, s_w1t, &s_b1v, w1, b1);
    int b  = blockIdx.x >> 5;
    int l0 = (blockIdx.x & 31) << 10;
    stage_tiles<1024>(b, l0, s_ph0, s_ph1, s_ps0, s_ps1);
    __syncthreads();

    int li0 = threadIdx.x << 2;
    float ph0[4], ph1[4], ps0[12], ps1[12];
    load_windows(s_ph0, s_ph1, s_ps0, s_ps1, li0, ph0, ph1, ps0, ps1);
    float t[4][4];
    t4_compute(ph0, ph1, ps0, ps1, s_ac1, s_w1t, s_b1v, t);

    float acc[8];
    #pragma unroll
    for (int j = 0; j < 4; j++) {
        acc[j]   = t[0][j] + t[1][j] + t[2][j] + t[3][j];
        acc[4+j] = t[0][j]*t[0][j] + t[1][j]*t[1][j] + t[2][j]*t[2][j] + t[3][j]*t[3][j];
    }
    block_reduce_atomic<4>(acc, g_sum2, g_ssq2);

    if (last_block(&g_cnt2))
        finalize_bn<4>(g_sum2, g_ssq2, gim, beim, g_a2, g_c2, g_sum2, g_ssq2, &g_cnt2);
}

// P3: moments of weight*beta, materialize wb in-place ; last block finalizes BN3
__global__ void __launch_bounds__(256, 3) k_stats3(
        const float* __restrict__ w1, const float* __restrict__ b1,
        const float* __restrict__ w2, const float* __restrict__ b2,
        const float* __restrict__ gag, const float* __restrict__ beag) {
    __shared__ float2 s_ac1[16];
    __shared__ float4 s_w1t[16];
    __shared__ float4 s_b1v, s_a2v, s_c2v;
    __shared__ float4 s_w2v[8];
    __shared__ float s_b2[8];
    __shared__ __align__(16) float s_ph0[1024], s_ph1[1024], s_ps0[1040], s_ps1[1040];
    stage_params_t(s_ac1, s_w1t, &s_b1v, w1, b1);
    stage_params_2(s_w2v, s_b2, &s_a2v, &s_c2v, w2, b2);
    int b  = blockIdx.x >> 5;
    int l0 = (blockIdx.x & 31) << 10;
    stage_tiles<1024>(b, l0, s_ph0, s_ph1, s_ps0, s_ps1);
    __syncthreads();

    int li0 = threadIdx.x << 2;
    float ph0[4], ph1[4], ps0[12], ps1[12];
    load_windows(s_ph0, s_ph1, s_ps0, s_ps1, li0, ph0, ph1, ps0, ps1);
    float t[4][4];
    t4_compute(ph0, ph1, ps0, ps1, s_ac1, s_w1t, s_b1v, t);
    float w8[4][8];
    w8_compute(t, s_a2v, s_c2v, s_w2v, s_b2, w8);

    size_t base = (size_t)b * Ll + l0;
    float acc[16];
    #pragma unroll
    for (int k = 0; k < 16; k++) acc[k] = 0.f;
    #pragma unroll
    for (int e = 0; e < 4; e++) {
        size_t idx = base + li0 + e;
        float4 b0 = g_beta[2*idx], b1v = g_beta[2*idx+1];
        float wb[8];
        wb[0]=w8[e][0]*b0.x;  wb[1]=w8[e][1]*b0.y;  wb[2]=w8[e][2]*b0.z;  wb[3]=w8[e][3]*b0.w;
        wb[4]=w8[e][4]*b1v.x; wb[5]=w8[e][5]*b1v.y; wb[6]=w8[e][6]*b1v.z; wb[7]=w8[e][7]*b1v.w;
        g_beta[2*idx]   = make_float4(wb[0], wb[1], wb[2], wb[3]);
        g_beta[2*idx+1] = make_float4(wb[4], wb[5], wb[6], wb[7]);
        #pragma unroll
        for (int j = 0; j < 8; j++) { acc[j] += wb[j]; acc[8+j] += wb[j]*wb[j]; }
    }
    block_reduce_atomic<8>(acc, g_sum3, g_ssq3);

    if (last_block(&g_cnt3))
        finalize_bn<8>(g_sum3, g_ssq3, gag, beag, g_a3, g_c3, g_sum3, g_ssq3, &g_cnt3);
}

// load wb (stored in g_beta) and apply BN3 affine+relu -> ag[4][8]
__device__ __forceinline__ void load_aggr(const float2* s_ac3, size_t base, int li0,
        float ag[4][8]) {
    #pragma unroll
    for (int i = 0; i < 4; i++) {
        size_t idx = base + li0 + i;
        float4 w0 = g_beta[2*idx], w1 = g_beta[2*idx+1];
        float wb[8] = {w0.x, w0.y, w0.z, w0.w, w1.x, w1.y, w1.z, w1.w};
        #pragma unroll
        for (int o = 0; o < 8; o++) {
            float2 ac = s_ac3[o];
            ag[i][o] = fmaxf(fmaf(ac.x, wb[o], ac.y), 0.f);
        }
    }
}

__device__ __forceinline__ void stage_params_3(float2* s_ac3) {
    int t = threadIdx.x;
    if (t >= 48 && t < 56) s_ac3[t-48] = make_float2(g_a3[t-48], g_c3[t-48]);
}

// P4: moments of y = x + conv_out(aggr) ; last block finalizes BN4
__global__ void __launch_bounds__(256, 3) k_stats4(
        const float* __restrict__ x,
        const float* __restrict__ wo, const float* __restrict__ bo,
        const float* __restrict__ ghid, const float* __restrict__ behid) {
    __shared__ float2 s_ac3[8];
    __shared__ float s_wo[256], s_bo[32];
    __shared__ float part[8][64];
    stage_params_3(s_ac3);
    for (int i = threadIdx.x; i < 256; i += 256) s_wo[i] = wo[i];
    if (threadIdx.x >= 64 && threadIdx.x < 96) s_bo[threadIdx.x-64] = bo[threadIdx.x-64];
    int b  = blockIdx.x >> 5;
    int l0 = (blockIdx.x & 31) << 10;
    __syncthreads();

    size_t base = (size_t)b * Ll + l0;
    int li0 = threadIdx.x << 2;
    float ag[4][8];
    load_aggr(s_ac3, base, li0, ag);

    const float* xb = x + (size_t)b * Hh * Ll + l0 + li0;
    int lane = threadIdx.x & 31, warp = threadIdx.x >> 5;
    #pragma unroll 4
    for (int c = 0; c < 32; c++) {
        float4 xv = __ldcs(reinterpret_cast<const float4*>(xb + (size_t)c * Ll));
        float xa[4] = {xv.x, xv.y, xv.z, xv.w};
        float bc = s_bo[c];
        float s = 0.f, q = 0.f;
        #pragma unroll
        for (int i = 0; i < 4; i++) {
            float y = xa[i] + bc;
            #pragma unroll
            for (int o = 0; o < 8; o++) y = fmaf(s_wo[c*8+o], ag[i][o], y);
            s += y; q += y*y;
        }
        #pragma unroll
        for (int o = 16; o; o >>= 1) {
            s += __shfl_down_sync(0xffffffffu, s, o);
            q += __shfl_down_sync(0xffffffffu, q, o);
        }
        if (lane == 0) { part[warp][2*c] = s; part[warp][2*c+1] = q; }
    }
    __syncthreads();
    for (int j = threadIdx.x; j < 64; j += 256) {
        float s = 0.f;
        #pragma unroll
        for (int w = 0; w < 8; w++) s += part[w][j];
        if ((j & 1) == 0) atomicAdd(&g_sum4[j >> 1], (double)s);
        else              atomicAdd(&g_ssq4[j >> 1], (double)s);
    }

    if (last_block(&g_cnt4))
        finalize_bn<32>(g_sum4, g_ssq4, ghid, behid, g_a4, g_c4, g_sum4, g_ssq4, &g_cnt4);
}

// P5: final output. Pure streaming: wb + x -> out.
__global__ void __launch_bounds__(256, 3) k_out(
        const float* __restrict__ x,
        const float* __restrict__ wo, const float* __restrict__ bo,
        float* __restrict__ out) {
    __shared__ float2 s_ac3[8];
    __shared__ float2 s_ac4[32];
    __shared__ float s_wo[256], s_bo[32];
    stage_params_3(s_ac3);
    for (int i = threadIdx.x; i < 256; i += 256) s_wo[i] = wo[i];
    if (threadIdx.x >= 64 && threadIdx.x < 96) s_bo[threadIdx.x-64] = bo[threadIdx.x-64];
    if (threadIdx.x >= 96 && threadIdx.x < 128) {
        int c = threadIdx.x - 96;
        s_ac4[c] = make_float2(g_a4[c], g_c4[c]);
    }
    int b  = blockIdx.x >> 5;
    int l0 = (blockIdx.x & 31) << 10;
    __syncthreads();

    size_t base = (size_t)b * Ll + l0;
    int li0 = threadIdx.x << 2;
    float ag[4][8];
    load_aggr(s_ac3, base, li0, ag);

    const float* xb = x + (size_t)b * Hh * Ll + l0 + li0;
    float* ob = out + (size_t)b * Hh * Ll + l0 + li0;
    #pragma unroll 4
    for (int c = 0; c < 32; c++) {
        float4 xv = __ldcs(reinterpret_cast<const float4*>(xb + (size_t)c * Ll));
        float xa[4] = {xv.x, xv.y, xv.z, xv.w};
        float bc = s_bo[c];
        float2 ac4 = s_ac4[c];
        float oa[4];
        #pragma unroll
        for (int i = 0; i < 4; i++) {
            float y = xa[i] + bc;
            #pragma unroll
            for (int o = 0; o < 8; o++) y = fmaf(s_wo[c*8+o], ag[i][o], y);
            oa[i] = fmaxf(fmaf(ac4.x, y, ac4.y), 0.f);
        }
        __stcs(reinterpret_cast<float4*>(ob + (size_t)c * Ll),
               make_float4(oa[0], oa[1], oa[2], oa[3]));
    }
}

// ---------------- host ----------------
extern "C" void kernel_launch(void* const* d_in, const int* in_sizes, int n_in,
                              void* d_out, int out_size) {
    const float* x      = (const float*)d_in[0];
    const float* w_phi  = (const float*)d_in[1];
    const float* b_phi  = (const float*)d_in[2];
    const float* w_psi  = (const float*)d_in[3];
    const float* b_psi  = (const float*)d_in[4];
    const float* w_beta = (const float*)d_in[5];
    const float* b_beta = (const float*)d_in[6];
    const float* w_cw1  = (const float*)d_in[7];
    const float* b_cw1  = (const float*)d_in[8];
    const float* w_cw2  = (const float*)d_in[9];
    const float* b_cw2  = (const float*)d_in[10];
    const float* w_out  = (const float*)d_in[11];
    const float* b_out  = (const float*)d_in[12];
    const float* gcat   = (const float*)d_in[13];
    const float* becat  = (const float*)d_in[14];
    const float* gim    = (const float*)d_in[15];
    const float* beim   = (const float*)d_in[16];
    const float* gag    = (const float*)d_in[17];
    const float* beag   = (const float*)d_in[18];
    const float* ghid   = (const float*)d_in[19];
    const float* behid  = (const float*)d_in[20];
    float* out = (float*)d_out;

    k_proj<<<1024, 256>>>(x, w_phi, b_phi, w_psi, b_psi, w_beta, b_beta, gcat, becat);
    k_stats2<<<1024, 256>>>(w_cw1, b_cw1, gim, beim);
    k_stats3<<<1024, 256>>>(w_cw1, b_cw1, w_cw2, b_cw2, gag, beag);
    k_stats4<<<1024, 256>>>(x, w_out, b_out, ghid, behid);
    k_out<<<1024, 256>>>(x, w_out, b_out, out);
}